// round 17
// baseline (speedup 1.0000x reference)
#include <cuda_runtime.h>
#include <math.h>

typedef unsigned long long ull;

#define FEAT_DIM 360
#define MAXB     32
#define NT       256
#define TILE     32

__device__ float g_feat[MAXB * FEAT_DIM];

// ---------------- packed f32x2 helpers ----------------
__device__ __forceinline__ ull pack2(float lo, float hi) {
    ull r; asm("mov.b64 %0, {%1, %2};" : "=l"(r) : "f"(lo), "f"(hi)); return r;
}
__device__ __forceinline__ ull fma2(ull a, ull b, ull c) {
    ull r; asm("fma.rn.f32x2 %0, %1, %2, %3;" : "=l"(r) : "l"(a), "l"(b), "l"(c)); return r;
}
__device__ __forceinline__ ull mul2(ull a, ull b) {
    ull r; asm("mul.rn.f32x2 %0, %1, %2;" : "=l"(r) : "l"(a), "l"(b)); return r;
}
__device__ __forceinline__ ull add2(ull a, ull b) {
    ull r; asm("add.rn.f32x2 %0, %1, %2;" : "=l"(r) : "l"(a), "l"(b)); return r;
}
// (hi(a), lo(b)) -- exactly 2 register moves
__device__ __forceinline__ ull mid2(ull a, ull b) {
    ull r;
    asm("{\n\t"
        ".reg .b32 al, ah, bl, bh;\n\t"
        "mov.b64 {al, ah}, %1;\n\t"
        "mov.b64 {bl, bh}, %2;\n\t"
        "mov.b64 %0, {ah, bl};\n\t"
        "}" : "=l"(r) : "l"(a), "l"(b));
    return r;
}

#define C06P 0x3F19999A3F19999AULL   // (0.6f, 0.6f)
#define C04P 0x3ECCCCCD3ECCCCCDULL   // (0.4f, 0.4f)
#define ONE2 0x3F8000003F800000ULL   // (1.0f, 1.0f)

// lrelu(v) = 0.6*v + 0.4*|v|  (exact), branch-free packed
__device__ __forceinline__ ull lrelu2(ull v) {
    ull a = v & 0x7FFFFFFF7FFFFFFFULL;
    return fma2(a, (ull)C04P, mul2(v, (ull)C06P));
}

// ---------------- merged preamble: mean(thumb) + GEMV, one launch ----------------
#define FT 384
__global__ void feat_kernel(const float* __restrict__ thumb,
                            const float* __restrict__ Wm,
                            const float* __restrict__ bm, int HW) {
    int b = blockIdx.x;
    int tid = threadIdx.x;
    __shared__ float red[FT / 32][3];
    __shared__ float m[3];
    const float4* p = (const float4*)(thumb + (size_t)b * 3 * HW);
    int n4c = HW / 4;
    float s[3];
    #pragma unroll
    for (int c = 0; c < 3; c++) {
        float acc = 0.0f;
        for (int i = tid; i < n4c; i += FT) {
            float4 v = p[c * n4c + i];
            acc += (v.x + v.y) + (v.z + v.w);
        }
        s[c] = acc;
    }
    #pragma unroll
    for (int c = 0; c < 3; c++) {
        float v = s[c];
        #pragma unroll
        for (int o = 16; o > 0; o >>= 1) v += __shfl_down_sync(0xffffffffu, v, o);
        if ((tid & 31) == 0) red[tid >> 5][c] = v;
    }
    __syncthreads();
    if (tid == 0) {
        float inv = 1.0f / (float)HW;
        #pragma unroll
        for (int c = 0; c < 3; c++) {
            float t = 0.0f;
            #pragma unroll
            for (int w = 0; w < FT / 32; w++) t += red[w][c];
            m[c] = t * inv;
        }
    }
    __syncthreads();
    if (tid < FEAT_DIM) {
        g_feat[b * FEAT_DIM + tid] =
            m[0] * Wm[tid] + m[1] * Wm[FEAT_DIM + tid] + m[2] * Wm[2 * FEAT_DIM + tid]
            + bm[tid];
    }
}

// ---------------- 3x3 conv layer: vertical pair-of-pairs with row reuse ----------------
// Work item = two vertically adjacent output pairs (rows y0, y0+1, same x).
// Per ic: 4 source rows loaded ONCE (8 LDS.64 + 4 mid2) feed both outputs:
// output v uses rows ky+v. Data LDS per pair: 12 (vs 18), FMA order unchanged.
// wPack layout: [oc*27 + ic*9 + ky*3 + kx], bias at 81..83.
template <int S, int D, int ITEMS, bool STORE>
__device__ __forceinline__ void conv3_vpair(const float* __restrict__ src,
                                            float* __restrict__ dst,
                                            const ull* __restrict__ wPack,
                                            int tid, ull outReg[2][3]) {
    constexpr int PW = D / 2;            // pair columns
    constexpr int NB = D / 2;            // vertical bands (V=2; D even)
    constexpr int NI = NB * PW;          // total items
    #pragma unroll
    for (int it = 0; it < ITEMS; it++) {
        int q = tid + it * NT;
        bool active = ((it + 1) * NT <= NI) || (q < NI);
        if (active) {
            int band = q / PW, col = q - band * PW;
            int y0 = band * 2, x = col * 2;
            ull acc[2][3];
            #pragma unroll
            for (int oc = 0; oc < 3; oc++) {
                ull bb = wPack[81 + oc];
                acc[0][oc] = bb; acc[1][oc] = bb;
            }
            #pragma unroll
            for (int ic = 0; ic < 3; ic++) {
                // load 4 source rows once (batched -> good MLP)
                ull r[4][3];
                #pragma unroll
                for (int rr = 0; rr < 4; rr++) {
                    const float* s = src + ic * S * S + (y0 + rr) * S + x;
                    r[rr][0] = *(const ull*)s;
                    r[rr][2] = *(const ull*)(s + 2);
                    r[rr][1] = mid2(r[rr][0], r[rr][2]);
                }
                #pragma unroll
                for (int ky = 0; ky < 3; ky++) {
                    ull w0a = wPack[ 0 + ic * 9 + ky * 3 + 0];
                    ull w0b = wPack[ 0 + ic * 9 + ky * 3 + 1];
                    ull w0c = wPack[ 0 + ic * 9 + ky * 3 + 2];
                    ull w1a = wPack[27 + ic * 9 + ky * 3 + 0];
                    ull w1b = wPack[27 + ic * 9 + ky * 3 + 1];
                    ull w1c = wPack[27 + ic * 9 + ky * 3 + 2];
                    ull w2a = wPack[54 + ic * 9 + ky * 3 + 0];
                    ull w2b = wPack[54 + ic * 9 + ky * 3 + 1];
                    ull w2c = wPack[54 + ic * 9 + ky * 3 + 2];
                    #pragma unroll
                    for (int v = 0; v < 2; v++) {
                        ull* rv = r[ky + v];
                        acc[v][0] = fma2(w0a, rv[0], acc[v][0]);
                        acc[v][1] = fma2(w1a, rv[0], acc[v][1]);
                        acc[v][2] = fma2(w2a, rv[0], acc[v][2]);
                        acc[v][0] = fma2(w0b, rv[1], acc[v][0]);
                        acc[v][1] = fma2(w1b, rv[1], acc[v][1]);
                        acc[v][2] = fma2(w2b, rv[1], acc[v][2]);
                        acc[v][0] = fma2(w0c, rv[2], acc[v][0]);
                        acc[v][1] = fma2(w1c, rv[2], acc[v][1]);
                        acc[v][2] = fma2(w2c, rv[2], acc[v][2]);
                    }
                }
            }
            #pragma unroll
            for (int v = 0; v < 2; v++) {
                #pragma unroll
                for (int oc = 0; oc < 3; oc++) {
                    ull res = lrelu2(acc[v][oc]);
                    if (STORE) *(ull*)(dst + oc * D * D + (y0 + v) * D + x) = res;
                    else       outReg[v][oc] = res;
                }
            }
        }
    }
}

// ---------------- fused conv stack + attention (main + thumb merged) ----------------
__global__ __launch_bounds__(NT, 3) void conv_att_kernel(
    const float* __restrict__ xMain, const float* __restrict__ xThumb,
    float* __restrict__ outAll, int Hm, int B, int tRowM) {
    __shared__ __align__(16) float bufA[3 * 38 * 38];
    __shared__ __align__(16) float bufB[3 * 36 * 36];
    __shared__ ull sPack[FEAT_DIM];

    int mainTotal = B * tRowM * tRowM;
    int bid = blockIdx.x;
    const float* src; float* dst;
    int H, tRow, b, tile;
    if (bid < mainTotal) {
        int per = tRowM * tRowM;
        b = bid / per; tile = bid - b * per;
        H = Hm; tRow = tRowM;
        src = xMain + (size_t)b * 3 * H * H;
        dst = outAll + (size_t)b * 3 * H * H;
    } else {
        int r = bid - mainTotal;
        b = r >> 2; tile = r & 3;
        H = 64; tRow = 2;
        src = xThumb + (size_t)b * 3 * 64 * 64;
        dst = outAll + (size_t)B * 3 * Hm * Hm + (size_t)b * 3 * 64 * 64;
    }
    int ty = tile / tRow, tx = tile - ty * tRow;
    int y0t = ty * TILE, x0t = tx * TILE;
    int tid = threadIdx.x;

    // load input tile with halo 3 (zero-padded) -- overlaps feat kernel (PDL)
    for (int i = tid; i < 3 * 38 * 38; i += NT) {
        int c = i / 1444;
        int r = i - c * 1444;
        int y = r / 38, xx = r - y * 38;
        int gy = y0t - 3 + y, gx = x0t - 3 + xx;
        float v = 0.0f;
        if (gy >= 0 && gy < H && gx >= 0 && gx < H)
            v = __ldg(&src[((size_t)c * H + gy) * H + gx]);
        bufA[i] = v;
    }

    // wait for feat_kernel's g_feat writes, then splat features
    cudaGridDependencySynchronize();
    for (int j = tid; j < FEAT_DIM; j += NT) {
        float f = g_feat[b * FEAT_DIM + j];
        sPack[j] = pack2(f, f);
    }
    __syncthreads();

    // L1: bufA(38) -> bufB(36), 324 items (tid<68 takes a 2nd)
    conv3_vpair<38, 36, 2, true>(bufA, bufB, sPack, tid, (ull(*)[3])nullptr);

    // stash residual pairs for this thread's two L3 output rows before bufA reuse
    int ey0 = (tid >> 4) * 2;          // output rows ey0, ey0+1
    int ex  = (tid & 15) * 2;          // output pair column
    ull resP[2][3];
    #pragma unroll
    for (int v = 0; v < 2; v++) {
        #pragma unroll
        for (int oc = 0; oc < 3; oc++) {
            const float* q = &bufA[(oc * 38 + 3 + ey0 + v) * 38 + 2 + ex];
            ull e0 = *(const ull*)q;
            ull e1 = *(const ull*)(q + 2);
            resP[v][oc] = mid2(e0, e1);
        }
    }
    __syncthreads();

    // L2: bufB(36) -> bufA(34), 289 items (tid<33 takes a 2nd)
    conv3_vpair<36, 34, 2, true>(bufB, bufA, sPack + 84, tid, (ull(*)[3])nullptr);
    __syncthreads();

    // L3: bufA(34) -> registers, exactly 256 items (1/thread: rows ey0/ey0+1, col ex)
    ull cur[2][3];
    conv3_vpair<34, 32, 1, false>(bufA, (float*)nullptr, sPack + 168, tid, cur);

    // 5x conv1x1 (packed, in registers; weights shared across both rows)
    #pragma unroll
    for (int l = 0; l < 5; l++) {
        const ull* wl = sPack + 252 + l * 12;
        ull W0 = wl[0], W1 = wl[1], W2 = wl[2];
        ull W3 = wl[3], W4 = wl[4], W5 = wl[5];
        ull W6 = wl[6], W7 = wl[7], W8 = wl[8];
        ull B0 = wl[9], B1 = wl[10], B2 = wl[11];
        #pragma unroll
        for (int v = 0; v < 2; v++) {
            ull c0 = cur[v][0], c1 = cur[v][1], c2 = cur[v][2];
            ull n0 = fma2(W0, c0, fma2(W1, c1, fma2(W2, c2, B0)));
            ull n1 = fma2(W3, c0, fma2(W4, c1, fma2(W5, c2, B1)));
            ull n2 = fma2(W6, c0, fma2(W7, c1, fma2(W8, c2, B2)));
            cur[v][0] = lrelu2(n0);
            cur[v][1] = lrelu2(n1);
            cur[v][2] = lrelu2(n2);
        }
    }
    // residual add
    #pragma unroll
    for (int v = 0; v < 2; v++)
        #pragma unroll
        for (int oc = 0; oc < 3; oc++)
            cur[v][oc] = add2(resP[v][oc], cur[v][oc]);

    // polynomial attention + store: poly coeffs loaded once for both rows;
    // wP shared (same column), hP per row.
    {
        float invH = 1.0f / (float)H;
        int gx = x0t + ex;
        ull wP = pack2((float)gx * invH, (float)(gx + 1) * invH);
        int gy0 = y0t + ey0;
        ull hP0 = pack2((float)gy0 * invH, (float)gy0 * invH);
        ull hP1 = pack2((float)(gy0 + 1) * invH, (float)(gy0 + 1) * invH);
        #pragma unroll
        for (int oc = 0; oc < 3; oc++) {
            ull v0 = cur[0][oc];
            ull v1 = cur[1][oc];
            ull att0 = (ull)ONE2, att1 = (ull)ONE2;
            #pragma unroll
            for (int i = 0; i < 4; i++) {
                const ull* f = sPack + 312 + oc * 16 + i * 4;
                ull F0 = f[0], F1 = f[1], F2 = f[2], F3 = f[3];
                att0 = mul2(att0, fma2(F0, hP0, fma2(F1, wP, fma2(F2, v0, F3))));
                att1 = mul2(att1, fma2(F0, hP1, fma2(F1, wP, fma2(F2, v1, F3))));
            }
            ull r0 = mul2(v0, add2((ull)ONE2, att0));
            ull r1 = mul2(v1, add2((ull)ONE2, att1));
            *(ull*)&dst[((size_t)oc * H + gy0) * H + gx]     = r0;
            *(ull*)&dst[((size_t)oc * H + gy0 + 1) * H + gx] = r1;
        }
    }
}

// ---------------- launch ----------------
extern "C" void kernel_launch(void* const* d_in, const int* in_sizes, int n_in,
                              void* d_out, int out_size) {
    const float* x     = (const float*)d_in[0];
    const float* thumb = (const float*)d_in[1];
    const float* Wm    = (const float*)d_in[2];
    const float* bm    = (const float*)d_in[3];
    float* out = (float*)d_out;

    int Ht = 64;
    int B  = in_sizes[1] / (3 * Ht * Ht);
    if (B < 1) B = 1;
    if (B > MAXB) B = MAXB;
    int hw = in_sizes[0] / (3 * B);
    int Hm = (int)(sqrt((double)hw) + 0.5);

    feat_kernel<<<B, FT>>>(thumb, Wm, bm, Ht * Ht);

    int tRowM = Hm / TILE;
    int total = B * tRowM * tRowM + B * 4;

    cudaLaunchConfig_t cfg = {};
    cfg.gridDim = dim3(total);
    cfg.blockDim = dim3(NT);
    cfg.dynamicSmemBytes = 0;
    cfg.stream = 0;
    cudaLaunchAttribute attrs[1];
    attrs[0].id = cudaLaunchAttributeProgrammaticStreamSerialization;
    attrs[0].val.programmaticStreamSerializationAllowed = 1;
    cfg.attrs = attrs;
    cfg.numAttrs = 1;
    cudaLaunchKernelEx(&cfg, conv_att_kernel, x, thumb, out, Hm, B, tRowM);
}